// round 8
// baseline (speedup 1.0000x reference)
#include <cuda_runtime.h>
#include <cstdio>

#define NLATc 361
#define NLONc 720
#define MMc   361
#define LMAXc 360
#define CCH   256
#define ROWSc (CCH * NLATc)                    // 92416
#define XELEMS (CCH * NLATc * NLONc)           // 66539520
#define WELEMS (MMc * LMAXc * NLATc)           // 46915560
#define FELEMS (NLONc * MMc)                   // 259920
#define MCHUNK 64
#define SCRN  ((size_t)MCHUNK * ROWSc)         // per-chunk scratch elems

// Scratch (device globals — no allocations allowed)
__device__ float g_Fc[FELEMS];   // cos twiddles * scale
__device__ float g_Fs[FELEMS];   // -sin twiddles * scale
__device__ float g_Xre[SCRN];    // [m_local][row], row = c*361 + k
__device__ float g_Xim[SCRN];

// ---------------------------------------------------------------------------
__global__ void twiddle_kernel(size_t flim) {
    int idx = blockIdx.x * blockDim.x + threadIdx.x;
    if ((size_t)idx >= flim) return;
    int n = idx / MMc;
    int m = idx - n * MMc;
    int j = (n * m) % NLONc;           // theta = pi * j / 360
    float s, c;
    sincospif((float)j / 360.0f, &s, &c);
    const float scale = 6.28318530717958647692f / 720.0f;
    g_Fc[idx] = c * scale;
    g_Fs[idx] = -s * scale;
}

// ---------------------------------------------------------------------------
// Stage 1 (per m-chunk): dual GEMM over a 64-wide m tile. grid = (1, 1444).
// ---------------------------------------------------------------------------
__global__ __launch_bounds__(256)
void dft_kernel(const float* __restrict__ x, size_t xlim,
                int m_base, size_t flim, size_t scrlim) {
    __shared__ float As[64][17];     // [row][n]
    __shared__ float Bc[16][64];     // [n][m]
    __shared__ float Bs[16][64];

    const int tid  = threadIdx.x;
    const int row0 = blockIdx.y * 64;
    const int tx   = tid & 15;       // row fragment selector
    const int ty   = tid >> 4;       // m fragment selector

    float accR[4][4] = {};
    float accI[4][4] = {};

    for (int n0 = 0; n0 < NLONc; n0 += 16) {
        #pragma unroll
        for (int i = 0; i < 4; i++) {
            int lin = tid + i * 256;
            int r   = lin >> 4;
            int nn  = lin & 15;
            size_t gi = (size_t)(row0 + r) * NLONc + (n0 + nn);
            As[r][nn] = (gi < xlim) ? x[gi] : 0.f;
        }
        #pragma unroll
        for (int i = 0; i < 4; i++) {
            int lin = tid + i * 256;
            int nn  = lin >> 6;
            int mm  = lin & 63;
            int mg  = m_base + mm;
            float vc = 0.f, vs = 0.f;
            size_t gi = (size_t)(n0 + nn) * MMc + mg;
            if (mg < MMc && gi < flim) {
                vc = g_Fc[gi];
                vs = g_Fs[gi];
            }
            Bc[nn][mm] = vc;
            Bs[nn][mm] = vs;
        }
        __syncthreads();

        #pragma unroll
        for (int kk = 0; kk < 16; kk++) {
            float a[4], bc[4], bs[4];
            #pragma unroll
            for (int i = 0; i < 4; i++) a[i] = As[tx * 4 + i][kk];
            #pragma unroll
            for (int j = 0; j < 4; j++) {
                bc[j] = Bc[kk][ty * 4 + j];
                bs[j] = Bs[kk][ty * 4 + j];
            }
            #pragma unroll
            for (int i = 0; i < 4; i++)
                #pragma unroll
                for (int j = 0; j < 4; j++) {
                    accR[i][j] += a[i] * bc[j];
                    accI[i][j] += a[i] * bs[j];
                }
        }
        __syncthreads();
    }

    #pragma unroll
    for (int j = 0; j < 4; j++) {
        int ml = ty * 4 + j;
        if (m_base + ml >= MMc) continue;
        #pragma unroll
        for (int i = 0; i < 4; i++) {
            int row = row0 + tx * 4 + i;
            size_t o = (size_t)ml * ROWSc + row;
            if (o < scrlim) {
                g_Xre[o] = accR[i][j];
                g_Xim[o] = accI[i][j];
            }
        }
    }
}

// ---------------------------------------------------------------------------
// Stage 2 (per m-chunk): per-m Legendre GEMM.
// OUTPUT IS FLOAT32 REAL PART ONLY: out[(c*360+l)*361+m] = Re.
// Guard: o < olim where olim = out_size in 4-byte elements -> cannot fault.
// ---------------------------------------------------------------------------
__global__ __launch_bounds__(256)
void leg_kernel(const float* __restrict__ w, float* __restrict__ out,
                size_t wlim, size_t olim, int m_base, size_t scrlim) {
    const int ml = blockIdx.z;
    const int m  = m_base + ml;
    if (m >= MMc) return;

    __shared__ float Ar[64][17];     // [c][k]
    __shared__ float Ai[64][17];
    __shared__ float Ws[64][17];     // [l][k]

    const int tid = threadIdx.x;
    const int c0  = blockIdx.y * 64;
    const int l0  = blockIdx.x * 64;
    const int tx  = tid & 15;        // l fragment selector
    const int ty  = tid >> 4;        // c fragment selector

    float accR[4][4] = {};
    float accI[4][4] = {};

    const size_t abase = (size_t)ml * ROWSc;
    const size_t wbase = (size_t)m * LMAXc * NLATc;

    for (int k0 = 0; k0 < NLATc; k0 += 16) {
        #pragma unroll
        for (int i = 0; i < 4; i++) {
            int lin = tid + i * 256;
            int cc  = lin >> 4;
            int kk  = lin & 15;
            int k   = k0 + kk;
            float vr = 0.f, vi = 0.f;
            size_t gi = abase + (size_t)(c0 + cc) * NLATc + k;
            if (k < NLATc && gi < scrlim) {
                vr = g_Xre[gi];
                vi = g_Xim[gi];
            }
            Ar[cc][kk] = vr;
            Ai[cc][kk] = vi;
        }
        #pragma unroll
        for (int i = 0; i < 4; i++) {
            int lin = tid + i * 256;
            int ll  = lin >> 4;
            int kk  = lin & 15;
            int l   = l0 + ll;
            int k   = k0 + kk;
            float vw = 0.f;
            size_t gi = wbase + (size_t)l * NLATc + k;
            if (l < LMAXc && k < NLATc && gi < wlim)
                vw = w[gi];
            Ws[ll][kk] = vw;
        }
        __syncthreads();

        #pragma unroll
        for (int kk = 0; kk < 16; kk++) {
            float ar[4], ai[4], wv[4];
            #pragma unroll
            for (int i = 0; i < 4; i++) {
                ar[i] = Ar[ty * 4 + i][kk];
                ai[i] = Ai[ty * 4 + i][kk];
            }
            #pragma unroll
            for (int j = 0; j < 4; j++) wv[j] = Ws[tx * 4 + j][kk];
            #pragma unroll
            for (int i = 0; i < 4; i++)
                #pragma unroll
                for (int j = 0; j < 4; j++) {
                    accR[i][j] += ar[i] * wv[j];
                    accI[i][j] += ai[i] * wv[j];
                }
        }
        __syncthreads();
    }

    // REAL PART ONLY, strictly within out_size 4-byte elements.
    #pragma unroll
    for (int i = 0; i < 4; i++) {
        int c = c0 + ty * 4 + i;
        #pragma unroll
        for (int j = 0; j < 4; j++) {
            int l = l0 + tx * 4 + j;
            if (l < LMAXc && c < CCH) {
                size_t o = ((size_t)c * LMAXc + l) * MMc + m;
                if (o < olim)
                    out[o] = accR[i][j];
            }
        }
    }
}

// ---------------------------------------------------------------------------
extern "C" void kernel_launch(void* const* d_in, const int* in_sizes, int n_in,
                              void* d_out, int out_size) {
    // Bind by exact element count (confirmed by R5 diagnostics).
    const float* x = nullptr;
    const float* w = nullptr;
    size_t xsz = 0, wsz = 0;
    for (int i = 0; i < n_in; i++) {
        if (in_sizes[i] == XELEMS)      { x = (const float*)d_in[i]; xsz = (size_t)in_sizes[i]; }
        else if (in_sizes[i] == WELEMS) { w = (const float*)d_in[i]; wsz = (size_t)in_sizes[i]; }
    }
    if (!x || !w) return;

    float* out = (float*)d_out;
    size_t olim = (size_t)out_size;   // out_size elements of 4 bytes — conservative

    twiddle_kernel<<<(FELEMS + 255) / 256, 256>>>((size_t)FELEMS);

    for (int mb = 0; mb < MMc; mb += MCHUNK) {
        dim3 g1(1, ROWSc / 64);                        // 1 x 1444
        dft_kernel<<<g1, 256>>>(x, xsz, mb, (size_t)FELEMS, SCRN);

        dim3 g2((LMAXc + 63) / 64, CCH / 64, MCHUNK);  // 6 x 4 x 64
        leg_kernel<<<g2, 256>>>(w, out, wsz, olim, mb, SCRN);
    }
}

// round 9
// speedup vs baseline: 2.2704x; 2.2704x over previous
#include <cuda_runtime.h>

#define NLATc 361
#define NLONc 720
#define MMc   361
#define LMAXc 360
#define CCH   256
#define ROWSc (CCH * NLATc)                    // 92416
#define XELEMS (CCH * NLATc * NLONc)           // 66539520
#define WELEMS (MMc * LMAXc * NLATc)           // 46915560
#define KPAD  368                              // 361 folded-K padded to 16
#define FEL   (KPAD * MMc)                     // cos table elems
#define XFN   ((size_t)ROWSc * KPAD)           // folded x elems (136 MB)
#define SCRN  ((size_t)MMc * ROWSc)            // stage-1 out elems (133 MB)

// Device scratch (statics proven safe in R8)
__device__ float g_Fc[FEL];    // [j][m] cos(2*pi*j*m/720) * (2*pi/720), 0 for j>360
__device__ float g_Xf[XFN];    // folded x: [row][j]
__device__ float g_Xre[SCRN];  // Re(xf): [m][row], row = c*361 + k

// ---------------------------------------------------------------------------
// Cos table: F[j][m] = scale * cos(pi * (j*m mod 720) / 360), j in [0,361); 0-pad.
// ---------------------------------------------------------------------------
__global__ void twiddle_kernel() {
    int idx = blockIdx.x * blockDim.x + threadIdx.x;
    if (idx >= FEL) return;
    int j = idx / MMc;
    int m = idx - j * MMc;
    float v = 0.f;
    if (j <= 360) {
        int jm = (j * m) % NLONc;
        v = cospif((float)jm / 360.0f) * (6.28318530717958647692f / 720.0f);
    }
    g_Fc[idx] = v;
}

// ---------------------------------------------------------------------------
// Fold: xf[row][j] = x[row][j] + x[row][720-j] (j=1..359); passthrough j=0,360;
// zero j>360. Streaming, memory-bound.
// ---------------------------------------------------------------------------
__global__ void fold_kernel(const float* __restrict__ x, size_t xlim) {
    size_t idx = (size_t)blockIdx.x * blockDim.x + threadIdx.x;
    if (idx >= XFN) return;
    int j   = (int)(idx % KPAD);
    size_t row = idx / KPAD;
    float v = 0.f;
    if (j <= 360) {
        size_t b = row * NLONc;
        size_t i0 = b + j;
        v = (i0 < xlim) ? x[i0] : 0.f;
        if (j >= 1 && j <= 359) {
            size_t i1 = b + (NLONc - j);
            v += (i1 < xlim) ? x[i1] : 0.f;
        }
    }
    g_Xf[idx] = v;
}

// ---------------------------------------------------------------------------
// Stage 1: Re(xf)[m][row] = sum_j xf[row][j] * Fc[j][m].
// GEMM M=92416 (rows), N=361 (m), K=368. BM=64, BN=64, BK=16, 4x4 frags.
// ---------------------------------------------------------------------------
__global__ __launch_bounds__(256)
void dft_kernel() {
    __shared__ float As[64][17];     // [row][j]
    __shared__ float Bc[16][64];     // [j][m]

    const int tid  = threadIdx.x;
    const int row0 = blockIdx.y * 64;
    const int m0   = blockIdx.x * 64;
    const int tx   = tid & 15;       // row fragment selector
    const int ty   = tid >> 4;       // m fragment selector

    float acc[4][4] = {};

    for (int n0 = 0; n0 < KPAD; n0 += 16) {
        #pragma unroll
        for (int i = 0; i < 4; i++) {
            int lin = tid + i * 256;
            int r   = lin >> 4;
            int nn  = lin & 15;
            As[r][nn] = g_Xf[(size_t)(row0 + r) * KPAD + (n0 + nn)];
        }
        {
            int nn = tid >> 6;               // 0..3 (4 j-rows per pass)
            int mm = tid & 63;
            #pragma unroll
            for (int i = 0; i < 4; i++) {
                int jr = n0 + nn + i * 4;
                int mg = m0 + mm;
                Bc[nn + i * 4][mm] = (mg < MMc) ? g_Fc[jr * MMc + mg] : 0.f;
            }
        }
        __syncthreads();

        #pragma unroll
        for (int kk = 0; kk < 16; kk++) {
            float a[4], b[4];
            #pragma unroll
            for (int i = 0; i < 4; i++) a[i] = As[tx * 4 + i][kk];
            #pragma unroll
            for (int j = 0; j < 4; j++) b[j] = Bc[kk][ty * 4 + j];
            #pragma unroll
            for (int i = 0; i < 4; i++)
                #pragma unroll
                for (int j = 0; j < 4; j++)
                    acc[i][j] += a[i] * b[j];
        }
        __syncthreads();
    }

    #pragma unroll
    for (int j = 0; j < 4; j++) {
        int m = m0 + ty * 4 + j;
        if (m >= MMc) continue;
        #pragma unroll
        for (int i = 0; i < 4; i++) {
            int row = row0 + tx * 4 + i;
            g_Xre[(size_t)m * ROWSc + row] = acc[i][j];
        }
    }
}

// ---------------------------------------------------------------------------
// Stage 2: out[c,l,m] = sum_k Xre[m][c][k] * W[m][l][k]  (real only).
// Per-m GEMM: BM=64 c, BN=64 l, BK=16, 4x4 frags. grid (6, 4, 361).
// ---------------------------------------------------------------------------
__global__ __launch_bounds__(256)
void leg_kernel(const float* __restrict__ w, float* __restrict__ out,
                size_t wlim, size_t olim) {
    const int m  = blockIdx.z;

    __shared__ float Ar[64][17];     // [c][k]
    __shared__ float Ws[64][17];     // [l][k]

    const int tid = threadIdx.x;
    const int c0  = blockIdx.y * 64;
    const int l0  = blockIdx.x * 64;
    const int tx  = tid & 15;        // l fragment selector
    const int ty  = tid >> 4;        // c fragment selector

    float acc[4][4] = {};

    const size_t abase = (size_t)m * ROWSc;
    const size_t wbase = (size_t)m * LMAXc * NLATc;

    for (int k0 = 0; k0 < NLATc; k0 += 16) {
        #pragma unroll
        for (int i = 0; i < 4; i++) {
            int lin = tid + i * 256;
            int cc  = lin >> 4;
            int kk  = lin & 15;
            int k   = k0 + kk;
            Ar[cc][kk] = (k < NLATc)
                ? g_Xre[abase + (size_t)(c0 + cc) * NLATc + k] : 0.f;
        }
        #pragma unroll
        for (int i = 0; i < 4; i++) {
            int lin = tid + i * 256;
            int ll  = lin >> 4;
            int kk  = lin & 15;
            int l   = l0 + ll;
            int k   = k0 + kk;
            float vw = 0.f;
            size_t gi = wbase + (size_t)l * NLATc + k;
            if (l < LMAXc && k < NLATc && gi < wlim)
                vw = w[gi];
            Ws[ll][kk] = vw;
        }
        __syncthreads();

        #pragma unroll
        for (int kk = 0; kk < 16; kk++) {
            float a[4], b[4];
            #pragma unroll
            for (int i = 0; i < 4; i++) a[i] = Ar[ty * 4 + i][kk];
            #pragma unroll
            for (int j = 0; j < 4; j++) b[j] = Ws[tx * 4 + j][kk];
            #pragma unroll
            for (int i = 0; i < 4; i++)
                #pragma unroll
                for (int j = 0; j < 4; j++)
                    acc[i][j] += a[i] * b[j];
        }
        __syncthreads();
    }

    #pragma unroll
    for (int i = 0; i < 4; i++) {
        int c = c0 + ty * 4 + i;
        #pragma unroll
        for (int j = 0; j < 4; j++) {
            int l = l0 + tx * 4 + j;
            if (l < LMAXc && c < CCH) {
                size_t o = ((size_t)c * LMAXc + l) * MMc + m;
                if (o < olim)
                    out[o] = acc[i][j];
            }
        }
    }
}

// ---------------------------------------------------------------------------
extern "C" void kernel_launch(void* const* d_in, const int* in_sizes, int n_in,
                              void* d_out, int out_size) {
    const float* x = nullptr;
    const float* w = nullptr;
    size_t xsz = 0, wsz = 0;
    for (int i = 0; i < n_in; i++) {
        if (in_sizes[i] == XELEMS)      { x = (const float*)d_in[i]; xsz = (size_t)in_sizes[i]; }
        else if (in_sizes[i] == WELEMS) { w = (const float*)d_in[i]; wsz = (size_t)in_sizes[i]; }
    }
    if (!x || !w) return;

    float* out = (float*)d_out;
    size_t olim = (size_t)out_size;    // float32 elements (real part only)

    twiddle_kernel<<<(FEL + 255) / 256, 256>>>();

    fold_kernel<<<(int)((XFN + 255) / 256), 256>>>(x, xsz);

    dim3 g1((MMc + 63) / 64, ROWSc / 64);      // 6 x 1444
    dft_kernel<<<g1, 256>>>();

    dim3 g2((LMAXc + 63) / 64, CCH / 64, MMc); // 6 x 4 x 361
    leg_kernel<<<g2, 256>>>(w, out, wsz, olim);
}

// round 14
// speedup vs baseline: 4.1262x; 1.8174x over previous
#include <cuda_runtime.h>
#include <cuda_bf16.h>
#include <cstdint>

#define CCH   256
#define NLAT  361
#define NLON  720
#define MM    361
#define LMAX  360
#define ROWS  (CCH * NLAT)            // 92416
#define KP    384
#define KS    (KP / 16)               // 24 k-steps
#define QTOT  (CCH * LMAX)            // 92160
#define XELEMS (CCH * NLAT * NLON)    // 66539520
#define WELEMS (MM * LMAX * NLAT)     // 46915560
#define SMEMSZ 49152                  // 2 buffers x 4 tiles x 6144B

// Packed bf16 hi|lo<<16 operands (BSS zero => zero pads stay zero)
__device__ uint32_t g_Fp[KP * KP];                 // [m][j]
__device__ uint32_t g_Xfp[(size_t)ROWS * KP];      // [row][j]
__device__ uint32_t g_Xp[(size_t)MM * CCH * KP];   // [m][c][k]
__device__ uint32_t g_Wp[(size_t)MM * KP * KP];    // [m][l][k]
__device__ float    g_Csc[(size_t)MM * QTOT];      // [m][c*360+l]

__device__ __forceinline__ uint32_t pack_f32(float v) {
    __nv_bfloat16 h = __float2bfloat16(v);
    __nv_bfloat16 l = __float2bfloat16(v - __bfloat162float(h));
    return (uint32_t)__bfloat16_as_ushort(h)
         | ((uint32_t)__bfloat16_as_ushort(l) << 16);
}

__device__ __forceinline__ uint32_t smem_u32(const void* p) {
    uint32_t a;
    asm("{ .reg .u64 t; cvta.to.shared.u64 t, %1; cvt.u32.u64 %0, t; }"
        : "=r"(a) : "l"(p));
    return a;
}
__device__ __forceinline__ void ldsm4(uint32_t* r, uint32_t a) {
    asm volatile("ldmatrix.sync.aligned.m8n8.x4.shared.b16 {%0,%1,%2,%3}, [%4];"
        : "=r"(r[0]), "=r"(r[1]), "=r"(r[2]), "=r"(r[3]) : "r"(a));
}
__device__ __forceinline__ void mma16816(float* c, const uint32_t* a,
                                         const uint32_t* b) {
    asm volatile("mma.sync.aligned.m16n8k16.row.col.f32.bf16.bf16.f32 "
        "{%0,%1,%2,%3}, {%4,%5,%6,%7}, {%8,%9}, {%0,%1,%2,%3};"
        : "+f"(c[0]), "+f"(c[1]), "+f"(c[2]), "+f"(c[3])
        : "r"(a[0]), "r"(a[1]), "r"(a[2]), "r"(a[3]), "r"(b[0]), "r"(b[1]));
}
#define STS128(a, r0, r1, r2, r3) \
    asm volatile("st.shared.v4.b32 [%0], {%1,%2,%3,%4};" \
        :: "r"(a), "r"(r0), "r"(r1), "r"(r2), "r"(r3) : "memory")

// ---------------- prep kernels ---------------------------------------------
__global__ void k_twiddle() {
    int idx = blockIdx.x * blockDim.x + threadIdx.x;
    if (idx >= KP * KP) return;
    int m = idx / KP, j = idx - m * KP;
    float v = 0.f;
    if (m < MM && j <= 360)
        v = cospif((float)((j * m) % NLON) / 360.0f)
            * (6.28318530717958647692f / 720.0f);
    g_Fp[idx] = pack_f32(v);
}

__global__ void k_fold(const float* __restrict__ x, size_t xlim) {
    size_t idx = (size_t)blockIdx.x * blockDim.x + threadIdx.x;
    if (idx >= (size_t)ROWS * KP) return;
    int j = (int)(idx % KP);
    size_t row = idx / KP;
    float v = 0.f;
    if (j <= 360) {
        size_t b = row * NLON;
        size_t i0 = b + j;
        v = (i0 < xlim) ? x[i0] : 0.f;
        if (j >= 1 && j <= 359) {
            size_t i1 = b + (NLON - j);
            v += (i1 < xlim) ? x[i1] : 0.f;
        }
    }
    g_Xfp[idx] = pack_f32(v);
}

__global__ void k_wsplit(const float* __restrict__ w, size_t wlim) {
    size_t idx = (size_t)blockIdx.x * blockDim.x + threadIdx.x;
    if (idx >= (size_t)MM * KP * KP) return;
    int k = (int)(idx % KP);
    size_t t = idx / KP;
    int l = (int)(t % KP);
    int m = (int)(t / KP);
    float v = 0.f;
    if (l < LMAX && k < NLAT) {
        size_t gi = ((size_t)m * LMAX + l) * NLAT + k;
        if (gi < wlim) v = w[gi];
    }
    g_Wp[idx] = pack_f32(v);
}

// ---------------- unified GEMM: C[128,128] = A[128,K] . B[128,K]^T ---------
// smem buffer layout (per buffer, 24576B): Ah@0  Al@6144  Bh@12288  Bl@18432
// rows stored with 48B stride (16 bf16 data + 16B pad) -> ldmatrix conflict-free
struct Stage { uint4 a0, a1, b0, b1; };

__device__ __forceinline__ void ld_stage(Stage& s, const uint32_t* gA,
                                         const uint32_t* gB, int ks) {
    const uint4* pa = reinterpret_cast<const uint4*>(gA + ks * 16);
    s.a0 = pa[0]; s.a1 = pa[1];
    const uint4* pb = reinterpret_cast<const uint4*>(gB + ks * 16);
    s.b0 = pb[0]; s.b1 = pb[1];
}
__device__ __forceinline__ void st_pair(uint32_t dhi, uint32_t dlo,
                                        uint4 v0, uint4 v1) {
    uint32_t h0 = __byte_perm(v0.x, v0.y, 0x5410);
    uint32_t h1 = __byte_perm(v0.z, v0.w, 0x5410);
    uint32_t h2 = __byte_perm(v1.x, v1.y, 0x5410);
    uint32_t h3 = __byte_perm(v1.z, v1.w, 0x5410);
    uint32_t l0 = __byte_perm(v0.x, v0.y, 0x7632);
    uint32_t l1 = __byte_perm(v0.z, v0.w, 0x7632);
    uint32_t l2 = __byte_perm(v1.x, v1.y, 0x7632);
    uint32_t l3 = __byte_perm(v1.z, v1.w, 0x7632);
    STS128(dhi, h0, h1, h2, h3);
    STS128(dlo, l0, l1, l2, l3);
}
__device__ __forceinline__ void st_stage(const Stage& s, uint32_t buf,
                                         uint32_t fdst) {
    st_pair(buf + fdst,         buf + 6144  + fdst, s.a0, s.a1);
    st_pair(buf + 12288 + fdst, buf + 18432 + fdst, s.b0, s.b1);
}

__global__ __launch_bounds__(256, 1)
void k_gemm(int mode, size_t olim_unused) {
    extern __shared__ char smem[];
    const uint32_t sb = smem_u32(smem);
    const int tid = threadIdx.x;
    const int wid = tid >> 5, lane = tid & 31;
    const int warp_m = wid >> 2, warp_n = wid & 3;
    const int nb = blockIdx.x, mb = blockIdx.y, bz = blockIdx.z;

    const uint32_t* Aro;
    const uint32_t* Bro;
    if (mode == 0) {
        Aro = g_Xfp + (size_t)mb * 128 * KP;
        Bro = g_Fp  + (size_t)nb * 128 * KP;
    } else {
        Aro = g_Xp + ((size_t)bz * CCH + mb * 128) * KP;
        Bro = g_Wp + ((size_t)bz * KP  + nb * 128) * KP;
    }

    // fill mapping: lane-contiguous rows (conflict-free STS phases)
    const int frow  = tid & 127;
    const int fhalf = tid >> 7;
    const uint32_t fdst = frow * 48 + fhalf * 16;
    const uint32_t* gA = Aro + (size_t)frow * KP + fhalf * 8;
    const uint32_t* gB = Bro + (size_t)frow * KP + fhalf * 8;

    // ldmatrix lane offsets
    const uint32_t aoff = (warp_m * 64 + (lane & 15)) * 48 + (lane >> 4) * 16;
    const uint32_t boff = (warp_n * 32 + ((lane >> 4) << 3) + (lane & 7)) * 48
                        + ((lane >> 3) & 1) * 16;

    float acc[4][4][4];
    #pragma unroll
    for (int a = 0; a < 4; a++)
        #pragma unroll
        for (int b = 0; b < 4; b++)
            #pragma unroll
            for (int e = 0; e < 4; e++) acc[a][b][e] = 0.f;

    {   // prologue: fill buffer 0
        Stage s;
        ld_stage(s, gA, gB, 0);
        st_stage(s, sb, fdst);
    }
    __syncthreads();

    for (int ks = 0; ks < KS; ks++) {
        const uint32_t buf = sb + (ks & 1) * 24576;
        Stage s;
        const bool more = (ks + 1 < KS);
        if (more) ld_stage(s, gA, gB, ks + 1);   // hide gmem behind compute

        uint32_t Ah[4][4], Al[4][4], Bh[2][4], Bl[2][4];
        #pragma unroll
        for (int mi = 0; mi < 4; mi++) {
            ldsm4(Ah[mi], buf + aoff + mi * 768);
            ldsm4(Al[mi], buf + 6144 + aoff + mi * 768);
        }
        #pragma unroll
        for (int p = 0; p < 2; p++) {
            ldsm4(Bh[p], buf + 12288 + boff + p * 768);
            ldsm4(Bl[p], buf + 18432 + boff + p * 768);
        }
        #pragma unroll
        for (int mi = 0; mi < 4; mi++)
            #pragma unroll
            for (int ni = 0; ni < 4; ni++) {
                const int p = ni >> 1, q = (ni & 1) * 2;
                mma16816(acc[mi][ni], Ah[mi], &Bh[p][q]);
                mma16816(acc[mi][ni], Ah[mi], &Bl[p][q]);
                mma16816(acc[mi][ni], Al[mi], &Bh[p][q]);
            }

        if (more) st_stage(s, sb + ((ks + 1) & 1) * 24576, fdst);
        __syncthreads();
    }

    // epilogue
    const int r0 = lane >> 2;
    const int cq = (lane & 3) * 2;
    #pragma unroll
    for (int mi = 0; mi < 4; mi++) {
        #pragma unroll
        for (int ni = 0; ni < 4; ni++) {
            const int rbase = mb * 128 + warp_m * 64 + mi * 16 + r0;
            const int nbase = nb * 128 + warp_n * 32 + ni * 8 + cq;
            #pragma unroll
            for (int e = 0; e < 4; e++) {
                const int rr = rbase + (e >> 1) * 8;
                const int nn = nbase + (e & 1);
                const float v = acc[mi][ni][e];
                if (mode == 0) {
                    if (nn < MM) {
                        const int c = rr / NLAT;
                        const int k = rr - c * NLAT;
                        g_Xp[((size_t)nn * CCH + c) * KP + k] = pack_f32(v);
                    }
                } else {
                    if (nn < LMAX)
                        g_Csc[(size_t)bz * QTOT + (size_t)rr * LMAX + nn] = v;
                }
            }
        }
    }
}

// ---------------- transpose: out[(c*360+l)*361+m] = Csc[m][c*360+l] --------
__global__ void k_trans(float* __restrict__ out, size_t olim) {
    __shared__ float s[32][33];
    const int q0 = blockIdx.x * 32;
    const int m0 = blockIdx.y * 32;
    const int tx = threadIdx.x, ty = threadIdx.y;   // 32 x 8
    #pragma unroll
    for (int i = 0; i < 4; i++) {
        const int mm = m0 + ty + i * 8;
        s[ty + i * 8][tx] = (mm < MM)
            ? g_Csc[(size_t)mm * QTOT + q0 + tx] : 0.f;
    }
    __syncthreads();
    #pragma unroll
    for (int i = 0; i < 4; i++) {
        const int q = q0 + ty + i * 8;
        const int mm = m0 + tx;
        if (mm < MM) {
            const size_t o = (size_t)q * MM + mm;
            if (o < olim) out[o] = s[tx][ty + i * 8];
        }
    }
}

// ---------------------------------------------------------------------------
extern "C" void kernel_launch(void* const* d_in, const int* in_sizes, int n_in,
                              void* d_out, int out_size) {
    const float* x = nullptr;
    const float* w = nullptr;
    size_t xsz = 0, wsz = 0;
    for (int i = 0; i < n_in; i++) {
        if (in_sizes[i] == XELEMS)      { x = (const float*)d_in[i]; xsz = (size_t)in_sizes[i]; }
        else if (in_sizes[i] == WELEMS) { w = (const float*)d_in[i]; wsz = (size_t)in_sizes[i]; }
    }
    if (!x || !w) return;

    float* out = (float*)d_out;
    size_t olim = (size_t)out_size;

    cudaFuncSetAttribute(k_gemm, cudaFuncAttributeMaxDynamicSharedMemorySize,
                         SMEMSZ);

    k_twiddle<<<(KP * KP + 255) / 256, 256>>>();
    k_fold<<<(int)(((size_t)ROWS * KP + 255) / 256), 256>>>(x, xsz);
    k_wsplit<<<(int)(((size_t)MM * KP * KP + 255) / 256), 256>>>(w, wsz);

    k_gemm<<<dim3(3, ROWS / 128, 1), 256, SMEMSZ>>>(0, 0);      // stage 1
    k_gemm<<<dim3(3, CCH / 128, MM), 256, SMEMSZ>>>(1, 0);      // stage 2

    k_trans<<<dim3(QTOT / 32, (MM + 31) / 32), dim3(32, 8)>>>(out, olim);
}